// round 15
// baseline (speedup 1.0000x reference)
#include <cuda_runtime.h>
#include <math.h>

constexpr int N_OSC  = 2048;
constexpr int N_SAMP = 16384;
constexpr int LAT    = 32;
constexpr int HALF   = N_OSC * LAT;               // 65536

constexpr int OSC_CHUNK  = 32;
constexpr int KENT       = LAT + 2;                // 32 segs + pre(32) + post(33)
constexpr int SAMP_CHUNK = 1024;
constexpr int THREADS    = 256;
constexpr int SPT        = 4;
constexpr int N_OSC_BLK  = N_OSC / OSC_CHUNK;      // 64
constexpr int N_SAMP_BLK = N_SAMP / SAMP_CHUNK;    // 16
constexpr int POLY_ROWS  = 16;                     // rows 0..15 poly, 16..63 mufu

__device__ float    g_scratch[N_OSC_BLK * N_SAMP];   // 4 MB partials
__device__ unsigned g_cnt[N_SAMP_BLK];               // wraps 63->0: replay-safe

// sin(2*pi*r), r in [-0.5,0.5]: degree-9 odd poly (max err ~3e-5, validated R12)
constexpr float SA1 =  6.2831008f;
constexpr float SA3 = -41.332240f;
constexpr float SA5 =  81.374886f;
constexpr float SA7 = -74.511488f;
constexpr float SA9 =  32.841421f;
constexpr float MAGIC   = 12582912.0f;               // 1.5 * 2^23
constexpr float TWOPI_F = 6.28318530717958648f;

// -----------------------------------------------------------------------------
// BLOCK-LEVEL pipe specialization (R13/R14 lesson: thread-level hybrids pay
// register/instruction-stream overhead that swamps pipe balance; block-level
// keeps each path's lean profile and lets the SM scheduler overlap pipes
// across co-resident blocks).
//   blockIdx.y <  16: 32 oscillators via scalar degree-9 poly  (FMA pipe)
//   blockIdx.y >= 16: 32 oscillators via __sinf                (XU pipe)
// Tables: poly blocks store phase in cycles; mufu blocks pre-scaled by 2*pi.
// KENT entries per osc include pre(32)/post(33) rows -> branch-free loops.
// -----------------------------------------------------------------------------
__global__ __launch_bounds__(THREADS, 4)
void osc_kernel(const float* __restrict__ latent, float* __restrict__ out) {
    __shared__ float4 s_pk[OSC_CHUNK * KENT];  // (v, dv, dac, apadj)  ~17 KB
    __shared__ float  s_bu[OSC_CHUNK * KENT];  // phase base           ~4.3 KB
    __shared__ unsigned s_old;

    const int tid  = threadIdx.x;
    const int lane = tid & 31;
    const int warp = tid >> 5;
    const int oscBase = blockIdx.y * OSC_CHUNK;
    const bool isPoly = (blockIdx.y < POLY_ROWS);

    // ---- phase 0: |latent| passthrough ----
    if (tid < 32) {
        const int idx = ((blockIdx.y * N_SAMP_BLK + blockIdx.x) * 32 + tid) * 4;
        const int src = (idx < HALF) ? (HALF + idx) : (idx - HALF);
        const float4 v = *reinterpret_cast<const float4*>(&latent[src]);
        *reinterpret_cast<float4*>(&out[N_SAMP + idx]) =
            make_float4(fabsf(v.x), fabsf(v.y), fabsf(v.z), fabsf(v.w));
    }

    // ---- phase 1: fp32 warp-scan prologue, 8 warps x 4 oscillators ----
    const float S = isPoly ? 1.0f : TWOPI_F;      // block-uniform
#pragma unroll
    for (int j = 0; j < OSC_CHUNK / 8; ++j) {
        const int o  = warp * (OSC_CHUNK / 8) + j;
        const int go = oscBase + o;
        const float f  = fabsf(latent[(size_t)(N_OSC + go) * LAT + lane]);
        const float a  = fabsf(latent[(size_t)go * LAT + lane]);
        const float fn = __shfl_down_sync(0xffffffffu, f, 1);
        const float an = __shfl_down_sync(0xffffffffu, a, 1);
        const float df = (lane < 31) ? (fn - f) : 0.0f;
        const float da = (lane < 31) ? (an - a) : 0.0f;
        const float t = (lane < 31) ? 256.0f * (f + fn) : 0.0f;
        float sc = t;
#pragma unroll
        for (int d = 1; d < 32; d <<= 1) {
            const float u = __shfl_up_sync(0xffffffffu, sc, d);
            if (lane >= d) sc += u;
        }
        const float f0 = __shfl_sync(0xffffffffu, f, 0);
        const float C  = fmaf(256.0f, f0, sc - t);        // exclusive prefix C_k
        const float r  = fmaf(-2.0f, rintf(0.5f * C), C); // C mod 2, exact
        const float vf = S * f;
        const float dv = S * (df * (1.0f / 512.0f));
        const float bu = S * (0.5f * r);
        const float dac = da * (1.0f / 256.0f);
        const float aa  = fmaf(da, -0.0009765625f, a);    // ap - da/1024
        s_pk[o * KENT + lane] = make_float4(vf, dv, dac, aa);
        s_bu[o * KENT + lane] = bu;
        if (lane == 0) {                                  // pre entry (k=32)
            s_pk[o * KENT + 32] = make_float4(vf, 0.0f, 0.0f, a);
            s_bu[o * KENT + 32] = bu;
        }
        if (lane == 31) {                                 // post entry (k=33)
            s_pk[o * KENT + 33] = make_float4(vf, 0.0f, 0.0f, a);
            s_bu[o * KENT + 33] = bu;
        }
    }
    __syncthreads();

    // ---- per-thread sample constants: k and c1[s] only ----
    const int i0 = blockIdx.x * SAMP_CHUNK + tid * SPT;
    int k;
    float c1[SPT];
    if (i0 < 256) {
        k = 32;
#pragma unroll
        for (int s = 0; s < SPT; ++s) c1[s] = 0.5f * (float)(i0 + s - 255);
    } else if (i0 >= 16128) {
        k = 33;
#pragma unroll
        for (int s = 0; s < SPT; ++s) c1[s] = 0.5f * (float)(i0 + s - 16127);
    } else {
        k = (i0 - 256) >> 9;
        const int m0 = (i0 - 256) & 511;
#pragma unroll
        for (int s = 0; s < SPT; ++s) c1[s] = 0.5f * (float)(m0 + s + 1);
    }

    float acc[SPT] = {0.f, 0.f, 0.f, 0.f};
    const float4* pk = &s_pk[k];
    const float*  bk = &s_bu[k];

    if (!isPoly) {
        // ---- mufu main loop (exact R11 body, XU pipe) ----
#pragma unroll 4
        for (int o = 0; o < OSC_CHUNK; ++o) {
            const float4 p  = pk[o * KENT];            // (v, dv, dac, apadj)
            const float  bq = bk[o * KENT];
#pragma unroll
            for (int s = 0; s < SPT; ++s) {
                const float t   = fmaf(c1[s], p.y, p.x);
                const float Q   = fmaf(c1[s], t, bq);
                const float sv  = __sinf(Q);
                const float amp = fmaf(c1[s], p.z, p.w);
                acc[s] = fmaf(sv, amp, acc[s]);
            }
        }
    } else {
        // ---- poly main loop (scalar degree-9, FMA pipe, no MUFU) ----
#pragma unroll 4
        for (int o = 0; o < OSC_CHUNK; ++o) {
            const float4 p  = pk[o * KENT];
            const float  bq = bk[o * KENT];
#pragma unroll
            for (int s = 0; s < SPT; ++s) {
                const float t  = fmaf(c1[s], p.y, p.x);
                const float u  = fmaf(c1[s], t, bq);   // phase in cycles
                const float ri = (u + MAGIC) - MAGIC;  // rint(u), exact trick
                const float r  = u - ri;               // [-0.5, 0.5], exact
                const float z  = r * r;
                float h = fmaf(z, SA9, SA7);
                h = fmaf(h, z, SA5);
                h = fmaf(h, z, SA3);
                h = fmaf(h, z, SA1);
                const float sv  = h * r;
                const float amp = fmaf(c1[s], p.z, p.w);
                acc[s] = fmaf(sv, amp, acc[s]);
            }
        }
    }

    *reinterpret_cast<float4*>(&g_scratch[blockIdx.y * N_SAMP + i0]) =
        make_float4(acc[0], acc[1], acc[2], acc[3]);

    // ---- phase 3: last block per column reduces (fixed order = deterministic) ----
    __threadfence();
    __syncthreads();
    if (tid == 0)
        s_old = atomicInc(&g_cnt[blockIdx.x], N_OSC_BLK - 1);   // wraps 63 -> 0
    __syncthreads();

    if (s_old == N_OSC_BLK - 1) {
        __threadfence();
        const int j0 = blockIdx.x * SAMP_CHUNK + tid * 4;
        float4 a0 = make_float4(0.f, 0.f, 0.f, 0.f);
        float4 a1 = a0;
#pragma unroll
        for (int b = 0; b < N_OSC_BLK; b += 2) {
            const float4 v0 = *reinterpret_cast<const float4*>(&g_scratch[(b + 0) * N_SAMP + j0]);
            const float4 v1 = *reinterpret_cast<const float4*>(&g_scratch[(b + 1) * N_SAMP + j0]);
            a0.x += v0.x; a0.y += v0.y; a0.z += v0.z; a0.w += v0.w;
            a1.x += v1.x; a1.y += v1.y; a1.z += v1.z; a1.w += v1.w;
        }
        const float sc = 1.0f / (float)N_OSC;
        *reinterpret_cast<float4*>(&out[j0]) = make_float4(
            (a0.x + a1.x) * sc, (a0.y + a1.y) * sc,
            (a0.z + a1.z) * sc, (a0.w + a1.w) * sc);
    }
}

extern "C" void kernel_launch(void* const* d_in, const int* in_sizes, int n_in,
                              void* d_out, int out_size) {
    const float* latent = (const float*)d_in[n_in - 1];
    for (int i = 0; i < n_in; ++i) {
        if (in_sizes[i] == 2 * HALF) { latent = (const float*)d_in[i]; break; }
    }
    float* out = (float*)d_out;

    dim3 grid(N_SAMP_BLK, N_OSC_BLK);                       // 16 x 64 = 1024 blocks
    osc_kernel<<<grid, THREADS>>>(latent, out);
}

// round 16
// speedup vs baseline: 1.3249x; 1.3249x over previous
#include <cuda_runtime.h>
#include <math.h>

constexpr int N_OSC  = 2048;
constexpr int N_SAMP = 16384;
constexpr int LAT    = 32;
constexpr int HALF   = N_OSC * LAT;               // 65536

constexpr int OSC_CHUNK  = 32;
constexpr int KENT       = LAT + 2;                // 32 segs + pre(32) + post(33)
constexpr int SAMP_CHUNK = 1024;
constexpr int THREADS    = 256;
constexpr int SPT        = 4;
constexpr int N_OSC_BLK  = N_OSC / OSC_CHUNK;      // 64
constexpr int N_SAMP_BLK = N_SAMP / SAMP_CHUNK;    // 16

__device__ float    g_scratch[N_OSC_BLK * N_SAMP];   // 4 MB partials
__device__ unsigned g_cnt[N_SAMP_BLK];               // wraps 63->0: replay-safe

constexpr float TWOPI_F = 6.28318530717958648f;

// -----------------------------------------------------------------------------
// Fused kernel, R11 config (occ 6, 20KB smem), with the instruction stream
// stripped down (R15 accounting: issue slots were ~2x the visible math; the
// overhead is address IMADs from the KENT*20B stride + loop bookkeeping):
//   * tables TRANSPOSED to k-major: [k*OSC_CHUNK + o] -> the oscillator loop
//     walks contiguous float4/float with immediate-offset LDS, no IMADs
//   * oscillator loop FULLY UNROLLED: compile-time smem addresses, no branch
// Phase math (radians, pre-scaled 2*pi): Q = c1*(v + c1*dv) + b;
// amp = apadj + c1*dac.  4 FMA + 1 MUFU per (osc,sample).
// -----------------------------------------------------------------------------
__global__ __launch_bounds__(THREADS, 6)
void osc_kernel(const float* __restrict__ latent, float* __restrict__ out) {
    __shared__ float4 s_pk[KENT * OSC_CHUNK];  // k-major: (v, dv, dac, apadj) 17 KB
    __shared__ float  s_bu[KENT * OSC_CHUNK];  // k-major phase base           4.3 KB
    __shared__ unsigned s_old;

    const int tid  = threadIdx.x;
    const int lane = tid & 31;
    const int warp = tid >> 5;
    const int oscBase = blockIdx.y * OSC_CHUNK;

    // ---- phase 0: |latent| passthrough ----
    if (tid < 32) {
        const int idx = ((blockIdx.y * N_SAMP_BLK + blockIdx.x) * 32 + tid) * 4;
        const int src = (idx < HALF) ? (HALF + idx) : (idx - HALF);
        const float4 v = *reinterpret_cast<const float4*>(&latent[src]);
        *reinterpret_cast<float4*>(&out[N_SAMP + idx]) =
            make_float4(fabsf(v.x), fabsf(v.y), fabsf(v.z), fabsf(v.w));
    }

    // ---- phase 1: fp32 warp-scan prologue, 8 warps x 4 oscillators ----
#pragma unroll
    for (int j = 0; j < OSC_CHUNK / 8; ++j) {
        const int o  = warp * (OSC_CHUNK / 8) + j;
        const int go = oscBase + o;
        const float f  = fabsf(latent[(size_t)(N_OSC + go) * LAT + lane]);
        const float a  = fabsf(latent[(size_t)go * LAT + lane]);
        const float fn = __shfl_down_sync(0xffffffffu, f, 1);
        const float an = __shfl_down_sync(0xffffffffu, a, 1);
        const float df = (lane < 31) ? (fn - f) : 0.0f;
        const float da = (lane < 31) ? (an - a) : 0.0f;
        const float t = (lane < 31) ? 256.0f * (f + fn) : 0.0f;
        float sc = t;
#pragma unroll
        for (int d = 1; d < 32; d <<= 1) {
            const float u = __shfl_up_sync(0xffffffffu, sc, d);
            if (lane >= d) sc += u;
        }
        const float f0 = __shfl_sync(0xffffffffu, f, 0);
        const float C  = fmaf(256.0f, f0, sc - t);        // exclusive prefix C_k
        const float r  = fmaf(-2.0f, rintf(0.5f * C), C); // C mod 2, exact
        const float vf = TWOPI_F * f;
        const float dv = TWOPI_F * (df * (1.0f / 512.0f));
        const float bu = TWOPI_F * (0.5f * r);
        const float dac = da * (1.0f / 256.0f);
        const float aa  = fmaf(da, -0.0009765625f, a);    // ap - da/1024
        s_pk[lane * OSC_CHUNK + o] = make_float4(vf, dv, dac, aa);
        s_bu[lane * OSC_CHUNK + o] = bu;
        if (lane == 0) {                                  // pre entry (k=32)
            s_pk[32 * OSC_CHUNK + o] = make_float4(vf, 0.0f, 0.0f, a);
            s_bu[32 * OSC_CHUNK + o] = bu;
        }
        if (lane == 31) {                                 // post entry (k=33)
            s_pk[33 * OSC_CHUNK + o] = make_float4(vf, 0.0f, 0.0f, a);
            s_bu[33 * OSC_CHUNK + o] = bu;
        }
    }
    __syncthreads();

    // ---- per-thread sample constants: k and c1[s] only ----
    const int i0 = blockIdx.x * SAMP_CHUNK + tid * SPT;
    int k;
    float c1[SPT];
    if (i0 < 256) {
        k = 32;
#pragma unroll
        for (int s = 0; s < SPT; ++s) c1[s] = 0.5f * (float)(i0 + s - 255);
    } else if (i0 >= 16128) {
        k = 33;
#pragma unroll
        for (int s = 0; s < SPT; ++s) c1[s] = 0.5f * (float)(i0 + s - 16127);
    } else {
        k = (i0 - 256) >> 9;
        const int m0 = (i0 - 256) & 511;
#pragma unroll
        for (int s = 0; s < SPT; ++s) c1[s] = 0.5f * (float)(m0 + s + 1);
    }

    float acc[SPT] = {0.f, 0.f, 0.f, 0.f};
    // k-major base pointers: the unrolled loop below uses IMMEDIATE offsets
    const float4* pk = &s_pk[k * OSC_CHUNK];
    const float*  bk = &s_bu[k * OSC_CHUNK];

    // ---- phase 2: FULLY UNROLLED main loop (no IMADs, no branches) ----
#pragma unroll
    for (int o = 0; o < OSC_CHUNK; ++o) {
        const float4 p  = pk[o];                   // LDS.128 [pk + 16*o]
        const float  bq = bk[o];                   // LDS.32  [bk + 4*o]
#pragma unroll
        for (int s = 0; s < SPT; ++s) {
            const float t   = fmaf(c1[s], p.y, p.x);
            const float Q   = fmaf(c1[s], t, bq);
            const float sv  = __sinf(Q);
            const float amp = fmaf(c1[s], p.z, p.w);
            acc[s] = fmaf(sv, amp, acc[s]);
        }
    }

    *reinterpret_cast<float4*>(&g_scratch[blockIdx.y * N_SAMP + i0]) =
        make_float4(acc[0], acc[1], acc[2], acc[3]);

    // ---- phase 3: last block per column reduces (fixed order = deterministic) ----
    __threadfence();
    __syncthreads();
    if (tid == 0)
        s_old = atomicInc(&g_cnt[blockIdx.x], N_OSC_BLK - 1);   // wraps 63 -> 0
    __syncthreads();

    if (s_old == N_OSC_BLK - 1) {
        __threadfence();
        const int j0 = blockIdx.x * SAMP_CHUNK + tid * 4;
        float4 a0 = make_float4(0.f, 0.f, 0.f, 0.f);
        float4 a1 = a0;
#pragma unroll
        for (int b = 0; b < N_OSC_BLK; b += 2) {
            const float4 v0 = *reinterpret_cast<const float4*>(&g_scratch[(b + 0) * N_SAMP + j0]);
            const float4 v1 = *reinterpret_cast<const float4*>(&g_scratch[(b + 1) * N_SAMP + j0]);
            a0.x += v0.x; a0.y += v0.y; a0.z += v0.z; a0.w += v0.w;
            a1.x += v1.x; a1.y += v1.y; a1.z += v1.z; a1.w += v1.w;
        }
        const float sc = 1.0f / (float)N_OSC;
        *reinterpret_cast<float4*>(&out[j0]) = make_float4(
            (a0.x + a1.x) * sc, (a0.y + a1.y) * sc,
            (a0.z + a1.z) * sc, (a0.w + a1.w) * sc);
    }
}

extern "C" void kernel_launch(void* const* d_in, const int* in_sizes, int n_in,
                              void* d_out, int out_size) {
    const float* latent = (const float*)d_in[n_in - 1];
    for (int i = 0; i < n_in; ++i) {
        if (in_sizes[i] == 2 * HALF) { latent = (const float*)d_in[i]; break; }
    }
    float* out = (float*)d_out;

    dim3 grid(N_SAMP_BLK, N_OSC_BLK);                       // 16 x 64 = 1024 blocks
    osc_kernel<<<grid, THREADS>>>(latent, out);
}